// round 16
// baseline (speedup 1.0000x reference)
#include <cuda_runtime.h>
#include <cstdint>
#include <cstddef>

#define BATCH 128
#define SEQ   1024
#define DIN   512
#define HID   512

// transposed Wx: g_wt[j][k] = Wx[k][j]  (1MB, L2-resident)
__device__ __align__(16) float g_wt[HID * DIN];

typedef unsigned long long ull;
static __device__ __forceinline__ ull dup2(float a) {
    ull r; asm("mov.b64 %0, {%1, %1};" : "=l"(r) : "f"(a)); return r;
}
static __device__ __forceinline__ ull pack2(float a, float b) {
    ull r; asm("mov.b64 %0, {%1, %2};" : "=l"(r) : "f"(a), "f"(b)); return r;
}
static __device__ __forceinline__ void unpack2(ull v, float& lo, float& hi) {
    asm("mov.b64 {%0, %1}, %2;" : "=f"(lo), "=f"(hi) : "l"(v));
}
static __device__ __forceinline__ void fma2(ull& acc, ull a, ull b) {
    asm("fma.rn.f32x2 %0, %1, %2, %0;" : "+l"(acc) : "l"(a), "l"(b));
}
static __device__ __forceinline__ ull add2v(ull a, ull b) {
    ull r; asm("add.rn.f32x2 %0, %1, %2;" : "=l"(r) : "l"(a), "l"(b)); return r;
}
static __device__ __forceinline__ float fast_tanh(float x) {
    x = fminf(fmaxf(x, -12.0f), 12.0f);
    const float e = __expf(2.0f * x);
    return __fdividef(e - 1.0f, e + 1.0f);
}

// ============================================================
// Kernel 0: Wx transpose -> g_wt  (~50us)
// ============================================================
__global__ void wt_transpose(const float* __restrict__ Wx)
{
    __shared__ float tile[32][33];
    const int tx = threadIdx.x, ty = threadIdx.y;   // 32 x 8
    const int bx = blockIdx.x, by = blockIdx.y;     // 16 x 16
#pragma unroll
    for (int r = 0; r < 4; r++)
        tile[ty + r * 8][tx] = Wx[(size_t)(by * 32 + ty + r * 8) * HID + bx * 32 + tx];
    __syncthreads();
#pragma unroll
    for (int r = 0; r < 4; r++)
        g_wt[(size_t)(bx * 32 + ty + r * 8) * DIN + by * 32 + tx] = tile[tx][ty + r * 8];
}

// ============================================================
// Kernel B v16: fused scan — R15 protocol + inline xp production
//   per step t (in the ship->wait shadow): compute
//   xp[t+2] = x[t+2] @ Wx[:,mycols] + bias, via the same red
//   buffer + tree-reduce, into a 4-slot smem ring. x[t+3] staged
//   to smem. Separate gemm kernel & g_xp deleted.
// ============================================================
#define WHS_F   (512 * 64)       // 128KB
#define HB_F    (2 * 512 * 8)    //  32KB
#define RED_U   (4 * 16 * 64)    //  32KB  red[pair][ksl][col]
#define STG_U   (2 * 64 * 4)     //   4KB
#define XSTG_F  (512 * 8)        //  16KB  xstg[k][8 batches]
#define XPR_U   (4 * 64 * 4)     //   8KB  xpr[slot][col][pair]
#define SMEM_V16 (WHS_F*4 + HB_F*4 + RED_U*8 + STG_U*8 + XSTG_F*4 + XPR_U*8 + 128)
#define SLICE_TXB 2048u

static __device__ __forceinline__ void bar_wait_cta(uint32_t mb, uint32_t parity) {
    uint32_t done;
    asm volatile(
        "{\n\t.reg .pred p;\n\t"
        "mbarrier.try_wait.parity.acquire.cta.shared::cta.b64 p, [%1], %2;\n\t"
        "selp.b32 %0, 1, 0, p;\n\t}"
        : "=r"(done) : "r"(mb), "r"(parity) : "memory");
    if (!done) {
        asm volatile(
            "{\n\t.reg .pred P1;\n\t"
            "W_%=:\n\t"
            "mbarrier.try_wait.parity.acquire.cta.shared::cta.b64 P1, [%0], %1, 0x989680;\n\t"
            "@P1 bra.uni D_%=;\n\t"
            "bra.uni W_%=;\n\t"
            "D_%=:\n\t}"
            :: "r"(mb), "r"(parity) : "memory");
    }
}

__global__ void __launch_bounds__(512, 1) __cluster_dims__(8, 1, 1)
rnn_scan(const float* __restrict__ x,
         const float* __restrict__ Wh,
         const float* __restrict__ bias,
         float* __restrict__ out)
{
    extern __shared__ __align__(16) float smem[];
    float* Whs  = smem;                         // [512][64]
    float* hb   = smem + WHS_F;                 // [2][512][8]
    ull*   red  = (ull*)(hb + HB_F);            // [4][16][64]
    ull*   stg  = red + RED_U;                  // [2][64][4]
    float* xstg = (float*)(stg + STG_U);        // [512][8]
    ull*   xpr  = (ull*)(xstg + XSTG_F);        // [4][64][4]
    ull*   mbar = xpr + XPR_U;                  // [2 buf][8 src]

    const int tid  = threadIdx.x;
    const int rank = blockIdx.x & 7;
    const int cid  = blockIdx.x >> 3;
    const int ksl  = tid >> 5;                  // warp : k-slice
    const int c2   = tid & 31;                  // col-pair
    const int mysrc = ksl >> 1;

    uint32_t mbar_u32, hb_u32, stg_u32;
    asm("{ .reg .u64 t; cvta.to.shared.u64 t, %1; cvt.u32.u64 %0, t; }"
        : "=r"(mbar_u32) : "l"(mbar));
    asm("{ .reg .u64 t; cvta.to.shared.u64 t, %1; cvt.u32.u64 %0, t; }"
        : "=r"(hb_u32) : "l"(hb));
    asm("{ .reg .u64 t; cvta.to.shared.u64 t, %1; cvt.u32.u64 %0, t; }"
        : "=r"(stg_u32) : "l"(stg));

    for (int i = tid; i < 512 * 16; i += 512) {
        const int k = i >> 4, jv = i & 15;
        *(float4*)&Whs[k * 64 + jv * 4] =
            *(const float4*)&Wh[(size_t)k * HID + rank * 64 + jv * 4];
    }
    for (int i = tid; i < HB_F; i += 512) hb[i] = 0.0f;
    if (tid < 16) {
        const uint32_t mb = mbar_u32 + (uint32_t)(tid * 8);
        asm volatile("mbarrier.init.shared.b64 [%0], 1;" :: "r"(mb) : "memory");
        asm volatile("mbarrier.arrive.expect_tx.shared.b64 _, [%0], %1;"
                     :: "r"(mb), "r"(SLICE_TXB) : "memory");
    }

    const int rp = tid >> 6;                    // row-pair 0..3 (tid<256)
    const int c  = tid & 63;                    // col 0..63
    const int jg = rank * 64 + c;
    const int b0 = cid * 8 + 2 * rp;
    const float bv = (tid < 256) ? bias[jg] : 0.0f;

    uint32_t pdst[8], pbar[8];
#pragma unroll
    for (int r = 0; r < 8; r++) {
        const uint32_t la = hb_u32 + (uint32_t)(rank * 2048);
        asm("mapa.shared::cluster.u32 %0, %1, %2;" : "=r"(pdst[r]) : "r"(la), "r"(r));
        const uint32_t lb = mbar_u32 + (uint32_t)(rank * 8);
        asm("mapa.shared::cluster.u32 %0, %1, %2;" : "=r"(pbar[r]) : "r"(lb), "r"(r));
    }

    // ---- fused-gemm pointers (constant all steps) ----
    const float* w0p = g_wt + (size_t)(rank * 64 + 2 * c2) * DIN + ksl * 32;
    const float* w1p = w0p + DIN;
    const float* xk  = xstg + ksl * 32 * 8;     // this warp's k-slice of x
    const float* xbase = x + (size_t)(cid * 8) * SEQ * DIN;   // batch base

    asm volatile("barrier.cluster.arrive.aligned;" ::: "memory");
    asm volatile("barrier.cluster.wait.aligned;"   ::: "memory");

    // ========== helpers as macros (uniform control flow) ==========
#define STAGE_X(S) do {                                                   \
        float xr[8];                                                     \
        const float* xs_ = xbase + (size_t)(S) * DIN + tid;              \
        _Pragma("unroll")                                                \
        for (int b_ = 0; b_ < 8; b_++)                                   \
            xr[b_] = xs_[(size_t)b_ * SEQ * DIN];                        \
        float4 f0_, f1_;                                                 \
        f0_.x=xr[0]; f0_.y=xr[1]; f0_.z=xr[2]; f0_.w=xr[3];              \
        f1_.x=xr[4]; f1_.y=xr[5]; f1_.z=xr[6]; f1_.w=xr[7];              \
        *(float4*)&xstg[tid * 8]     = f0_;                              \
        *(float4*)&xstg[tid * 8 + 4] = f1_;                              \
    } while (0)

#define CHUNK_COMPUTE() do {                                              \
        ull ca[4][2];                                                    \
        _Pragma("unroll")                                                \
        for (int p_ = 0; p_ < 4; p_++) { ca[p_][0] = 0; ca[p_][1] = 0; } \
        _Pragma("unroll")                                                \
        for (int blk_ = 0; blk_ < 4; blk_++) {                           \
            const float4 wa0 = *(const float4*)(w0p + blk_ * 8);         \
            const float4 wa1 = *(const float4*)(w0p + blk_ * 8 + 4);     \
            const float4 wb0 = *(const float4*)(w1p + blk_ * 8);         \
            const float4 wb1 = *(const float4*)(w1p + blk_ * 8 + 4);     \
            const float wa_[8] = {wa0.x,wa0.y,wa0.z,wa0.w,wa1.x,wa1.y,wa1.z,wa1.w}; \
            const float wb_[8] = {wb0.x,wb0.y,wb0.z,wb0.w,wb1.x,wb1.y,wb1.z,wb1.w}; \
            _Pragma("unroll")                                            \
            for (int i_ = 0; i_ < 8; i_++) {                             \
                const int kk_ = blk_ * 8 + i_;                           \
                const ulonglong2 x01 = *(const ulonglong2*)(xk + kk_ * 8);     \
                const ulonglong2 x23 = *(const ulonglong2*)(xk + kk_ * 8 + 4); \
                const ull w0_ = dup2(wa_[i_]), w1_ = dup2(wb_[i_]);      \
                fma2(ca[0][0], x01.x, w0_); fma2(ca[1][0], x01.y, w0_);  \
                fma2(ca[2][0], x23.x, w0_); fma2(ca[3][0], x23.y, w0_);  \
                fma2(ca[0][1], x01.x, w1_); fma2(ca[1][1], x01.y, w1_);  \
                fma2(ca[2][1], x23.x, w1_); fma2(ca[3][1], x23.y, w1_);  \
            }                                                            \
        }                                                                \
        ulonglong2 v_;                                                   \
        v_.x = ca[0][0]; v_.y = ca[0][1];                                \
        *(ulonglong2*)&red[(0 * 16 + ksl) * 64 + 2 * c2] = v_;           \
        v_.x = ca[1][0]; v_.y = ca[1][1];                                \
        *(ulonglong2*)&red[(1 * 16 + ksl) * 64 + 2 * c2] = v_;           \
        v_.x = ca[2][0]; v_.y = ca[2][1];                                \
        *(ulonglong2*)&red[(2 * 16 + ksl) * 64 + 2 * c2] = v_;           \
        v_.x = ca[3][0]; v_.y = ca[3][1];                                \
        *(ulonglong2*)&red[(3 * 16 + ksl) * 64 + 2 * c2] = v_;           \
    } while (0)

#define CHUNK_REDUCE(SLOT) do {                                           \
        const ull* rb_ = red + (size_t)rp * (16 * 64) + c;               \
        ull s_[8];                                                       \
        _Pragma("unroll")                                                \
        for (int i_ = 0; i_ < 8; i_++)                                   \
            s_[i_] = add2v(rb_[(size_t)(2 * i_) * 64],                   \
                           rb_[(size_t)(2 * i_ + 1) * 64]);              \
        s_[0]=add2v(s_[0],s_[1]); s_[2]=add2v(s_[2],s_[3]);              \
        s_[4]=add2v(s_[4],s_[5]); s_[6]=add2v(s_[6],s_[7]);              \
        s_[0]=add2v(s_[0],s_[2]); s_[4]=add2v(s_[4],s_[6]);              \
        s_[0]=add2v(s_[0],s_[4]);                                        \
        float lo_, hi_; unpack2(s_[0], lo_, hi_);                        \
        xpr[(SLOT) * 256 + c * 4 + rp] = pack2(lo_ + bv, hi_ + bv);      \
    } while (0)

    // ========== prologue: xp[0], xp[1] into ring; xstg <- x[2] ==========
    STAGE_X(0); __syncthreads();
    CHUNK_COMPUTE(); __syncthreads();
    if (tid < 256) CHUNK_REDUCE(0);
    __syncthreads();
    STAGE_X(1); __syncthreads();
    CHUNK_COMPUTE(); __syncthreads();
    if (tid < 256) CHUNK_REDUCE(1);
    __syncthreads();
    STAGE_X(2); __syncthreads();

    const float* wp = Whs + (ksl * 32) * 64 + 2 * c2;
    const uint32_t mywait = mbar_u32 + (uint32_t)(mysrc * 8);

    for (int t = 0; t < SEQ; t++) {
        const int cur = t & 1, nb = cur ^ 1;
        const bool do_chunk  = (t <= SEQ - 3);   // produce xp[t+2]
        const bool do_refill = (t <= SEQ - 4);   // stage x[t+3]

        // xp for this step from the ring
        float xp0 = 0.f, xp1 = 0.f;
        if (tid < 256) {
            float lo, hi; unpack2(xpr[(t & 3) * 256 + c * 4 + rp], lo, hi);
            xp0 = lo; xp1 = hi;
        }

        // early-issue x[t+3] loads (DRAM latency hides behind wait+kloop)
        float xr[8];
        if (do_refill) {
            const float* xs_ = xbase + (size_t)(t + 3) * DIN + tid;
#pragma unroll
            for (int b_ = 0; b_ < 8; b_++)
                xr[b_] = xs_[(size_t)b_ * SEQ * DIN];
        }

        if (t > 0) {
            const uint32_t parity = (uint32_t)(((t - 1) >> 1) & 1);
            const uint32_t mb = mywait + (uint32_t)(cur * 64);
            bar_wait_cta(mb, parity);
            if ((ksl & 1) == 0 && c2 == 0) {
                asm volatile("mbarrier.arrive.expect_tx.shared.b64 _, [%0], %1;"
                             :: "r"(mb), "r"(SLICE_TXB) : "memory");
            }
        }

        // ---- h k-loop ----
        const ull* hc = (const ull*)(hb + cur * 4096) + (size_t)ksl * 32 * 4;
        ull a00=0, a01=0, a10=0, a11=0, a20=0, a21=0, a30=0, a31=0;
#pragma unroll 8
        for (int kk = 0; kk < 32; kk++) {
            const float2 w = *(const float2*)(wp + kk * 64);
            const ulonglong2 h01 = *(const ulonglong2*)(hc + kk * 4);
            const ulonglong2 h23 = *(const ulonglong2*)(hc + kk * 4 + 2);
            const ull w0 = dup2(w.x), w1 = dup2(w.y);
            fma2(a00, h01.x, w0); fma2(a01, h01.y, w0);
            fma2(a10, h23.x, w0); fma2(a11, h23.y, w0);
            fma2(a20, h01.x, w1); fma2(a21, h01.y, w1);
            fma2(a30, h23.x, w1); fma2(a31, h23.y, w1);
        }
        {   // h partials -> red[pair][ksl][col]
            ulonglong2 v;
            v.x = a00; v.y = a20;
            *(ulonglong2*)&red[(0 * 16 + ksl) * 64 + 2 * c2] = v;
            v.x = a01; v.y = a21;
            *(ulonglong2*)&red[(1 * 16 + ksl) * 64 + 2 * c2] = v;
            v.x = a10; v.y = a30;
            *(ulonglong2*)&red[(2 * 16 + ksl) * 64 + 2 * c2] = v;
            v.x = a11; v.y = a31;
            *(ulonglong2*)&red[(3 * 16 + ksl) * 64 + 2 * c2] = v;
        }
        __syncthreads();   // sync1

        if (tid < 256) {   // h reduce + tanh -> stg
            const ull* rbase = red + (size_t)rp * (16 * 64) + c;
            ull s[8];
#pragma unroll
            for (int i = 0; i < 8; i++)
                s[i] = add2v(rbase[(size_t)(2 * i) * 64], rbase[(size_t)(2 * i + 1) * 64]);
            s[0] = add2v(s[0], s[1]); s[2] = add2v(s[2], s[3]);
            s[4] = add2v(s[4], s[5]); s[6] = add2v(s[6], s[7]);
            s[0] = add2v(s[0], s[2]); s[4] = add2v(s[4], s[6]);
            s[0] = add2v(s[0], s[4]);
            float lo, hi; unpack2(s[0], lo, hi);
            const float v0 = fast_tanh(lo + xp0);
            const float v1 = fast_tanh(hi + xp1);
            stg[(size_t)nb * 256 + c * 4 + rp] = pack2(v0, v1);
        }
        __syncthreads();   // sync2 (red free)

        if (tid == 0) {    // ship h(t+1)
            asm volatile("fence.proxy.async.shared::cta;" ::: "memory");
            const uint32_t src  = stg_u32 + (uint32_t)(nb * 2048);
            const uint32_t doff = (uint32_t)(nb * 16384);
            const uint32_t boff = (uint32_t)(nb * 64);
#pragma unroll
            for (int r = 0; r < 8; r++) {
                asm volatile(
                    "cp.async.bulk.shared::cluster.shared::cta.mbarrier::complete_tx::bytes "
                    "[%0], [%1], %2, [%3];"
                    :: "r"(pdst[r] + doff), "r"(src), "r"(SLICE_TXB), "r"(pbar[r] + boff)
                    : "memory");
            }
        }
        // fused gemm chunk: xp[t+2] partials -> red (in the ship shadow)
        if (do_chunk) CHUNK_COMPUTE();
        __syncthreads();   // sync3

        if (do_chunk && tid < 256) CHUNK_REDUCE((t + 2) & 3);
        if (do_refill) {   // xstg <- x[t+3]
            float4 f0, f1;
            f0.x=xr[0]; f0.y=xr[1]; f0.z=xr[2]; f0.w=xr[3];
            f1.x=xr[4]; f1.y=xr[5]; f1.z=xr[6]; f1.w=xr[7];
            *(float4*)&xstg[tid * 8]     = f0;
            *(float4*)&xstg[tid * 8 + 4] = f1;
        }
        __syncthreads();   // sync4 (red + xstg settled)
    }

    bar_wait_cta(mywait, 1u);
    __syncthreads();
    if (tid < 256) {
        const float2 hv = *(const float2*)&hb[jg * 8 + 2 * rp];
        out[(size_t)b0 * HID + jg]       = hv.x;
        out[(size_t)(b0 + 1) * HID + jg] = hv.y;
    }

    asm volatile("barrier.cluster.arrive.aligned;" ::: "memory");
    asm volatile("barrier.cluster.wait.aligned;"   ::: "memory");
#undef STAGE_X
#undef CHUNK_COMPUTE
#undef CHUNK_REDUCE
}

// ============================================================
extern "C" void kernel_launch(void* const* d_in, const int* in_sizes, int n_in,
                              void* d_out, int out_size)
{
    (void)in_sizes; (void)n_in; (void)out_size;
    const float* x    = (const float*)d_in[0];
    const float* Wx   = (const float*)d_in[1];
    const float* Wh   = (const float*)d_in[2];
    const float* bias = (const float*)d_in[3];
    float* out = (float*)d_out;

    cudaFuncSetAttribute(rnn_scan, cudaFuncAttributeMaxDynamicSharedMemorySize, SMEM_V16);

    wt_transpose<<<dim3(16, 16), dim3(32, 8)>>>(Wx);
    rnn_scan<<<128, 512, SMEM_V16>>>(x, Wh, bias, out);
}